// round 2
// baseline (speedup 1.0000x reference)
#include <cuda_runtime.h>

// Inverse 2D Haar DWT, collapsed to the per-2x2-block butterfly:
//   out[2i  ,2j  ] = 0.5*(LL + LH + HL + HH)
//   out[2i  ,2j+1] = 0.5*(LL - LH + HL - HH)
//   out[2i+1,2j  ] = 0.5*(LL + LH - HL - HH)
//   out[2i+1,2j+1] = 0.5*(LL - LH - HL + HH)
//
// Shapes: in (32,128,56,56) f32 x4 -> out (32,128,112,112) f32
// Each thread: float4 (streaming) load from each subband = 4 input cols,
// producing 8 output cols x 2 rows = 4x float4 streaming stores.

#define H_IN   56
#define W_IN   56
#define H_OUT  112
#define W_OUT  112
#define WQUADS (W_IN / 4)   // 14

__global__ __launch_bounds__(256)
void idwt_haar_kernel(const float* __restrict__ LL,
                      const float* __restrict__ LH,
                      const float* __restrict__ HL,
                      const float* __restrict__ HH,
                      float* __restrict__ out,
                      int total)   // = N*C*H_IN*WQUADS
{
    int idx = blockIdx.x * blockDim.x + threadIdx.x;
    if (idx >= total) return;

    int jj = idx % WQUADS;                 // input col quad -> cols 4jj..4jj+3
    int t  = idx / WQUADS;
    int i  = t % H_IN;                     // input row
    int ch = t / H_IN;                     // fused (batch*channel)

    long in_off  = (long)ch * (H_IN * W_IN) + i * W_IN + 4 * jj;
    long out_off = (long)ch * (H_OUT * W_OUT) + (2 * i) * W_OUT + 8 * jj;

    float4 ll = __ldcs(reinterpret_cast<const float4*>(LL + in_off));
    float4 lh = __ldcs(reinterpret_cast<const float4*>(LH + in_off));
    float4 hl = __ldcs(reinterpret_cast<const float4*>(HL + in_off));
    float4 hh = __ldcs(reinterpret_cast<const float4*>(HH + in_off));

    float a[4] = {ll.x, ll.y, ll.z, ll.w};
    float b[4] = {lh.x, lh.y, lh.z, lh.w};
    float c[4] = {hl.x, hl.y, hl.z, hl.w};
    float d[4] = {hh.x, hh.y, hh.z, hh.w};

    float ev[8], od[8];
    #pragma unroll
    for (int k = 0; k < 4; k++) {
        float p = a[k] + c[k];   // LL + HL
        float m = a[k] - c[k];   // LL - HL
        float q = b[k] + d[k];   // LH + HH
        float r = b[k] - d[k];   // LH - HH
        ev[2 * k]     = 0.5f * (p + q);
        ev[2 * k + 1] = 0.5f * (p - q);
        od[2 * k]     = 0.5f * (m + r);
        od[2 * k + 1] = 0.5f * (m - r);
    }

    float* oe = out + out_off;
    float* oo = out + out_off + W_OUT;
    __stcs(reinterpret_cast<float4*>(oe),     make_float4(ev[0], ev[1], ev[2], ev[3]));
    __stcs(reinterpret_cast<float4*>(oe) + 1, make_float4(ev[4], ev[5], ev[6], ev[7]));
    __stcs(reinterpret_cast<float4*>(oo),     make_float4(od[0], od[1], od[2], od[3]));
    __stcs(reinterpret_cast<float4*>(oo) + 1, make_float4(od[4], od[5], od[6], od[7]));
}

extern "C" void kernel_launch(void* const* d_in, const int* in_sizes, int n_in,
                              void* d_out, int out_size)
{
    const float* LL = (const float*)d_in[0];
    const float* LH = (const float*)d_in[1];
    const float* HL = (const float*)d_in[2];
    const float* HH = (const float*)d_in[3];
    float* out = (float*)d_out;

    int total = in_sizes[0] / 4;   // 32*128*56*56 / 4 = 3,211,264
    int threads = 256;
    int blocks = (total + threads - 1) / threads;

    idwt_haar_kernel<<<blocks, threads>>>(LL, LH, HL, HH, out, total);
}

// round 3
// speedup vs baseline: 1.0686x; 1.0686x over previous
#include <cuda_runtime.h>

// Inverse 2D Haar DWT, collapsed to the per-2x2-block butterfly:
//   out[2i  ,2j  ] = 0.5*(LL + LH + HL + HH)
//   out[2i  ,2j+1] = 0.5*(LL - LH + HL - HH)
//   out[2i+1,2j  ] = 0.5*(LL + LH - HL - HH)
//   out[2i+1,2j+1] = 0.5*(LL - LH - HL + HH)
//
// Shapes: in (32,128,56,56) f32 x4 -> out (32,128,112,112) f32
// R1 access pattern (best): float2 loads (perfectly linear across grid),
// two float4 stores per thread, each consecutive across the warp
// (512B/warp/instruction). Plus streaming cache hints: zero reuse, so
// evict-first on both loads and stores.

#define H_IN   56
#define W_IN   56
#define H_OUT  112
#define W_OUT  112
#define WPAIRS (W_IN / 2)   // 28

__global__ __launch_bounds__(256)
void idwt_haar_kernel(const float* __restrict__ LL,
                      const float* __restrict__ LH,
                      const float* __restrict__ HL,
                      const float* __restrict__ HH,
                      float* __restrict__ out,
                      int total)   // = N*C*H_IN*WPAIRS
{
    int idx = blockIdx.x * blockDim.x + threadIdx.x;
    if (idx >= total) return;

    int jj = idx % WPAIRS;                 // input col pair -> cols 2jj, 2jj+1
    int t  = idx / WPAIRS;
    int i  = t % H_IN;                     // input row
    int ch = t / H_IN;                     // fused (batch*channel)

    long in_off  = 2L * idx;               // loads are perfectly linear
    long out_off = (long)ch * (H_OUT * W_OUT) + (2 * i) * W_OUT + 4 * jj;

    float2 ll = __ldcs(reinterpret_cast<const float2*>(LL + in_off));
    float2 lh = __ldcs(reinterpret_cast<const float2*>(LH + in_off));
    float2 hl = __ldcs(reinterpret_cast<const float2*>(HL + in_off));
    float2 hh = __ldcs(reinterpret_cast<const float2*>(HH + in_off));

    // butterfly, element 0
    float p0 = ll.x + hl.x, m0 = ll.x - hl.x;
    float q0 = lh.x + hh.x, r0 = lh.x - hh.x;
    // butterfly, element 1
    float p1 = ll.y + hl.y, m1 = ll.y - hl.y;
    float q1 = lh.y + hh.y, r1 = lh.y - hh.y;

    float4 row_even = make_float4(0.5f * (p0 + q0), 0.5f * (p0 - q0),
                                  0.5f * (p1 + q1), 0.5f * (p1 - q1));
    float4 row_odd  = make_float4(0.5f * (m0 + r0), 0.5f * (m0 - r0),
                                  0.5f * (m1 + r1), 0.5f * (m1 - r1));

    __stcs(reinterpret_cast<float4*>(out + out_off),         row_even);
    __stcs(reinterpret_cast<float4*>(out + out_off + W_OUT), row_odd);
}

extern "C" void kernel_launch(void* const* d_in, const int* in_sizes, int n_in,
                              void* d_out, int out_size)
{
    const float* LL = (const float*)d_in[0];
    const float* LH = (const float*)d_in[1];
    const float* HL = (const float*)d_in[2];
    const float* HH = (const float*)d_in[3];
    float* out = (float*)d_out;

    int total = in_sizes[0] / 2;   // 32*128*56*56 / 2 = 6,422,528
    int threads = 256;
    int blocks = (total + threads - 1) / threads;

    idwt_haar_kernel<<<blocks, threads>>>(LL, LH, HL, HH, out, total);
}